// round 6
// baseline (speedup 1.0000x reference)
#include <cuda_runtime.h>
#include <cstdint>

// Problem constants (match reference generator)
#define BB    8            // batch
#define HH    32
#define WW    32
#define TT    4
#define BSs   3
#define DD    768
#define CELL_F4 ((BSs*DD)/4)   // 576 float4 per cell (2304 floats)
#define THREADS 192            // 3 float4 per thread
#define BLOCKS_PER_SM 10
#define NSM 148
#define GRID (NSM * BLOCKS_PER_SM)   // persistent: exactly one wave

// Persistent patch-centric expand. Each block loops grid-stride over patches:
// load the patch's 2304 floats once into registers (streaming), store them to
// every (s x s) cell the patch covers (streaming stores, never re-read).
// Output layout: [B, H, W, T, BS, D] -> cell index ((b*H+y)*W+x)*T+t.
// The position tiling partitions the grid, so every output cell is written
// exactly once per launch (deterministic across graph replays).
__global__ __launch_bounds__(THREADS, BLOCKS_PER_SM)
void apt_expand_kernel(const float4* __restrict__ tok,
                       const int*    __restrict__ positions,
                       float4*       __restrict__ out,
                       int P, int BP) {
    const int tix = threadIdx.x;

    int i = blockIdx.x;
    // Prime first position load
    int4 r = (i < BP) ? __ldg((const int4*)(positions + (size_t)i * 4))
                      : make_int4(0, 0, 0, 0);

    for (; i < BP; ) {
        const int b = i / P;
        const int y = r.x, x = r.y, s = r.z, t = r.w;

        // Issue this patch's payload loads (coalesced, streaming: no reuse)
        const float4* src = tok + (size_t)i * CELL_F4;
        const float4 v0 = __ldcs(&src[tix]);
        const float4 v1 = __ldcs(&src[tix + THREADS]);
        const float4 v2 = __ldcs(&src[tix + 2 * THREADS]);

        // Prefetch next iteration's position while payload loads are in flight
        const int inext = i + GRID;
        if (inext < BP)
            r = __ldg((const int4*)(positions + (size_t)inext * 4));

        // Store to each covered cell (s is 1 or 2); evict-first streaming
        const size_t base_cell = ((size_t)b * HH + y) * WW + x;
        #pragma unroll 1
        for (int dy = 0; dy < s; ++dy) {
            #pragma unroll 1
            for (int dx = 0; dx < s; ++dx) {
                const size_t cell = (base_cell + (size_t)dy * WW + dx) * TT + t;
                float4* dst = out + cell * CELL_F4;
                __stcs(&dst[tix],               v0);
                __stcs(&dst[tix + THREADS],     v1);
                __stcs(&dst[tix + 2 * THREADS], v2);
            }
        }

        i = inext;
    }
}

extern "C" void kernel_launch(void* const* d_in, const int* in_sizes, int n_in,
                              void* d_out, int out_size) {
    const float4* tok = (const float4*)d_in[0];     // modality_tokens [B, P*BS, D] fp32
    const int*    pos = (const int*)d_in[1];        // positions [B, P, 4] int32

    int P  = in_sizes[1] / (BB * 4);                // 2560
    int BP = BB * P;                                // 20480 patches

    apt_expand_kernel<<<GRID, THREADS>>>(tok, pos, (float4*)d_out, P, BP);
}

// round 7
// speedup vs baseline: 1.1780x; 1.1780x over previous
#include <cuda_runtime.h>
#include <cstdint>

// Problem constants (match reference generator)
#define BB    8            // batch
#define HH    32
#define WW    32
#define TT    4
#define BSs   3
#define DD    768
#define CELL_F4 ((BSs*DD)/4)   // 576 float4 per cell (2304 floats)
#define THREADS 192            // 3 float4 per thread

// Patch-centric: one block per patch (block turnover supplies MLP — a
// persistent variant measured slower). Load the patch's 2304 floats once
// into registers (streaming), store to every cell it covers.
// Output layout: [B, H, W, T, BS, D] -> cell index ((b*H+y)*W+x)*T+t.
// The position tiling partitions the grid, so every output cell is written
// exactly once per launch (deterministic across graph replays).
__global__ __launch_bounds__(THREADS, 10)
void apt_expand_kernel(const float4* __restrict__ tok,
                       const int*    __restrict__ positions,
                       float4*       __restrict__ out,
                       int P) {
    const int i = blockIdx.x;              // patch index over B*P
    const int b = i / P;
    const int tix = threadIdx.x;

    const int4 r = __ldg((const int4*)(positions + (size_t)i * 4));
    const int y = r.x, x = r.y, s = r.z, t = r.w;

    // Load this patch's payload once (coalesced, streaming: no reuse)
    const float4* src = tok + (size_t)i * CELL_F4;
    const float4 v0 = __ldcs(&src[tix]);
    const float4 v1 = __ldcs(&src[tix + THREADS]);
    const float4 v2 = __ldcs(&src[tix + 2 * THREADS]);

    const size_t cell0 = (((size_t)b * HH + y) * WW + x) * TT + t;
    float4* dst0 = out + cell0 * CELL_F4 + tix;

    if (s == 1) {
        // Fine patch (80% of blocks): single cell, straight-line stores
        __stcs(dst0,               v0);
        __stcs(dst0 + THREADS,     v1);
        __stcs(dst0 + 2 * THREADS, v2);
    } else {
        // Coarse 2x2 patch: 4 cells at constant offsets, all 12 stores ILP'd
        const size_t dX = (size_t)TT * CELL_F4;        // +1 in x
        const size_t dY = (size_t)WW * TT * CELL_F4;   // +1 in y
        float4* d00 = dst0;
        float4* d01 = dst0 + dX;
        float4* d10 = dst0 + dY;
        float4* d11 = dst0 + dY + dX;
        __stcs(d00,               v0);
        __stcs(d01,               v0);
        __stcs(d10,               v0);
        __stcs(d11,               v0);
        __stcs(d00 + THREADS,     v1);
        __stcs(d01 + THREADS,     v1);
        __stcs(d10 + THREADS,     v1);
        __stcs(d11 + THREADS,     v1);
        __stcs(d00 + 2 * THREADS, v2);
        __stcs(d01 + 2 * THREADS, v2);
        __stcs(d10 + 2 * THREADS, v2);
        __stcs(d11 + 2 * THREADS, v2);
    }
}

extern "C" void kernel_launch(void* const* d_in, const int* in_sizes, int n_in,
                              void* d_out, int out_size) {
    const float4* tok = (const float4*)d_in[0];     // modality_tokens [B, P*BS, D] fp32
    const int*    pos = (const int*)d_in[1];        // positions [B, P, 4] int32

    int P = in_sizes[1] / (BB * 4);                 // 2560

    apt_expand_kernel<<<BB * P, THREADS>>>(tok, pos, (float4*)d_out, P);
}

// round 8
// speedup vs baseline: 1.1785x; 1.0004x over previous
#include <cuda_runtime.h>
#include <cstdint>

// Problem constants (match reference generator)
#define BB    8            // batch
#define HH    32
#define WW    32
#define TT    4
#define BSs   3
#define DD    768
#define CELL_F4 ((BSs*DD)/4)   // 576 float4 per cell (2304 floats)
#define THREADS 192            // 3 float4 per thread per patch

// Store one patch payload (held in v0..v2) to the cells it covers.
__device__ __forceinline__
void store_patch(float4* __restrict__ out, int b, int y, int x, int s, int t,
                 int tix, const float4& v0, const float4& v1, const float4& v2) {
    const size_t cell0 = (((size_t)b * HH + y) * WW + x) * TT + t;
    float4* dst0 = out + cell0 * CELL_F4 + tix;
    if (s == 1) {
        __stcs(dst0,               v0);
        __stcs(dst0 + THREADS,     v1);
        __stcs(dst0 + 2 * THREADS, v2);
    } else {
        const size_t dX = (size_t)TT * CELL_F4;        // +1 in x
        const size_t dY = (size_t)WW * TT * CELL_F4;   // +1 in y
        float4* d00 = dst0;
        float4* d01 = dst0 + dX;
        float4* d10 = dst0 + dY;
        float4* d11 = dst0 + dY + dX;
        __stcs(d00,               v0);
        __stcs(d01,               v0);
        __stcs(d10,               v0);
        __stcs(d11,               v0);
        __stcs(d00 + THREADS,     v1);
        __stcs(d01 + THREADS,     v1);
        __stcs(d10 + THREADS,     v1);
        __stcs(d11 + THREADS,     v1);
        __stcs(d00 + 2 * THREADS, v2);
        __stcs(d01 + 2 * THREADS, v2);
        __stcs(d10 + 2 * THREADS, v2);
        __stcs(d11 + 2 * THREADS, v2);
    }
}

// Two patches per block: all 6 payload LDG.128 (two independent streams) are
// issued before any store, doubling per-warp front-batched MLP vs the
// one-patch version. Block turnover still supplies cross-block MLP.
// The position tiling partitions the grid, so every output cell is written
// exactly once per launch (deterministic across graph replays).
__global__ __launch_bounds__(THREADS, 7)
void apt_expand_kernel(const float4* __restrict__ tok,
                       const int*    __restrict__ positions,
                       float4*       __restrict__ out,
                       int P) {
    const int i0 = blockIdx.x * 2;         // first patch of this block's pair
    const int i1 = i0 + 1;
    const int tix = threadIdx.x;

    // Both position loads first
    const int4 ra = __ldg((const int4*)(positions + (size_t)i0 * 4));
    const int4 rb = __ldg((const int4*)(positions + (size_t)i1 * 4));

    // Front-batch all 6 payload loads (coalesced, streaming: no reuse)
    const float4* srcA = tok + (size_t)i0 * CELL_F4;
    const float4* srcB = tok + (size_t)i1 * CELL_F4;
    const float4 a0 = __ldcs(&srcA[tix]);
    const float4 a1 = __ldcs(&srcA[tix + THREADS]);
    const float4 a2 = __ldcs(&srcA[tix + 2 * THREADS]);
    const float4 b0 = __ldcs(&srcB[tix]);
    const float4 b1 = __ldcs(&srcB[tix + THREADS]);
    const float4 b2 = __ldcs(&srcB[tix + 2 * THREADS]);

    const int bA = i0 / P;
    const int bB = i1 / P;

    store_patch(out, bA, ra.x, ra.y, ra.z, ra.w, tix, a0, a1, a2);
    store_patch(out, bB, rb.x, rb.y, rb.z, rb.w, tix, b0, b1, b2);
}

extern "C" void kernel_launch(void* const* d_in, const int* in_sizes, int n_in,
                              void* d_out, int out_size) {
    const float4* tok = (const float4*)d_in[0];     // modality_tokens [B, P*BS, D] fp32
    const int*    pos = (const int*)d_in[1];        // positions [B, P, 4] int32

    int P  = in_sizes[1] / (BB * 4);                // 2560
    int BP = BB * P;                                // 20480 patches (even)

    apt_expand_kernel<<<BP / 2, THREADS>>>(tok, pos, (float4*)d_out, P);
}